// round 8
// baseline (speedup 1.0000x reference)
#include <cuda_runtime.h>
#include <cuda_bf16.h>
#include <cstdint>

#define B_  16
#define LQ_ 2048
#define S_  2048
#define D_  1024
#define K3QK 3072    // 3*D
#define K3A  6144    // 3*S == 3*LQ

// ------------- scratch (__device__ globals = allocation-guard-safe) -------------
static __device__ __nv_bfloat16 g_qs  [(size_t)B_ * LQ_ * K3QK];  // Q split  A-role [h|h|l]
static __device__ __nv_bfloat16 g_ks  [(size_t)B_ * S_  * K3QK];  // K split  B-role [h|l|h]
static __device__ __nv_bfloat16 g_vts [(size_t)B_ * D_  * K3A];   // V^T split B-role
static __device__ __nv_bfloat16 g_aws [(size_t)B_ * LQ_ * K3A];   // aw split  A-role
static __device__ __nv_bfloat16 g_awts[(size_t)B_ * S_  * K3A];   // aw^T split A-role
static __device__ __nv_bfloat16 g_o1ts[(size_t)B_ * D_  * K3A];   // out1^T split B-role

// ------------- PTX helpers (sm_100 baseline ISA: cp.async/ldmatrix/mma.sync) ----
__device__ __forceinline__ uint32_t smem_u32(const void* p) {
    uint32_t a;
    asm("{ .reg .u64 t; cvta.to.shared.u64 t, %1; cvt.u32.u64 %0, t; }" : "=r"(a) : "l"(p));
    return a;
}
#define CP_ASYNC16(dst, src) \
    asm volatile("cp.async.cg.shared.global [%0], [%1], 16;" :: "r"(dst), "l"(src) : "memory")
#define CP_COMMIT() asm volatile("cp.async.commit_group;" ::: "memory")
#define CP_WAIT1()  asm volatile("cp.async.wait_group 1;" ::: "memory")
#define CP_WAIT0()  asm volatile("cp.async.wait_group 0;" ::: "memory")

__device__ __forceinline__ void ldsm_x4(uint32_t& r0, uint32_t& r1, uint32_t& r2,
                                        uint32_t& r3, uint32_t addr) {
    asm volatile("ldmatrix.sync.aligned.m8n8.x4.shared.b16 {%0,%1,%2,%3}, [%4];"
                 : "=r"(r0), "=r"(r1), "=r"(r2), "=r"(r3) : "r"(addr));
}
__device__ __forceinline__ void mma_bf16(float* c, uint32_t a0, uint32_t a1,
                                         uint32_t a2, uint32_t a3,
                                         uint32_t b0, uint32_t b1) {
    asm volatile(
        "mma.sync.aligned.m16n8k16.row.col.f32.bf16.bf16.f32 "
        "{%0,%1,%2,%3}, {%4,%5,%6,%7}, {%8,%9}, {%0,%1,%2,%3};"
        : "+f"(c[0]), "+f"(c[1]), "+f"(c[2]), "+f"(c[3])
        : "r"(a0), "r"(a1), "r"(a2), "r"(a3), "r"(b0), "r"(b1));
}

// SMEM: 1KB align pad + max(2 stages x 48KB operands, 135168B epilogue slab)
static constexpr int SMEM_SZ = 1024 + 135168;
static constexpr int STAGE   = 49152;      // A 16KB + B 32KB per stage

// ------------- mma.sync GEMM: C[M,N] = scale * A[M,K3] @ B[N,K3]^T -------------
// CTA tile 128x256, 8 warps (2m x 4n), warp tile 64x64, K chunks of 64 bf16,
// SW128 xor-swizzle, cp.async double buffer.
// EPI=0: fp32 row-major C (ldc, scale). EPI=1: bf16 [h|l|h] transposed into Tg
//        with row pitch K3A (B-role split of C^T).
template<int EPI>
__global__ void __launch_bounds__(256, 1) gemm_mma(
    const __nv_bfloat16* __restrict__ Ag,
    const __nv_bfloat16* __restrict__ Bg,
    float* __restrict__ Cg, __nv_bfloat16* __restrict__ Tg,
    int K3, int ldc, size_t sA, size_t sB, size_t sOut, float scale)
{
    extern __shared__ char dsm[];
    const uint32_t raw  = smem_u32(dsm);
    const uint32_t base = (raw + 1023u) & ~1023u;
    char* sm = dsm + (base - raw);

    const int tid  = threadIdx.x;
    const int wid  = tid >> 5;
    const int lane = tid & 31;
    const int bm   = blockIdx.y * 128;
    const int bn   = blockIdx.x * 256;
    const __nv_bfloat16* A  = Ag + blockIdx.z * sA;
    const __nv_bfloat16* Bp = Bg + blockIdx.z * sB;

    const int wm = (wid & 1) * 64;         // warp m-offset
    const int wn = (wid >> 1) * 64;        // warp n-offset

    float acc[4][8][4];
    #pragma unroll
    for (int i = 0; i < 4; ++i)
        #pragma unroll
        for (int j = 0; j < 8; ++j)
            #pragma unroll
            for (int r = 0; r < 4; ++r) acc[i][j][r] = 0.f;

    const int lr  = tid >> 1;              // A load row 0..127
    const int lc0 = (tid & 1) << 2;        // A chunk base 0 or 4

    const int NT = K3 >> 6;

    auto load_chunk = [&](int kt, int buf) {
        const int kc = kt << 6;
        const uint32_t ab = base + buf * STAGE;
        const uint32_t bb = ab + 16384;
        const __nv_bfloat16* arow = A  + (size_t)(bm + lr) * K3 + kc;
        #pragma unroll
        for (int c = 0; c < 4; ++c) {      // A: 128 rows x 8 c16, 4/thread
            int c16 = lc0 + c;
            uint32_t sw = (uint32_t)((c16 ^ (lr & 7)) << 4);
            CP_ASYNC16(ab + (uint32_t)(lr << 7) + sw, arow + (c16 << 3));
        }
        const __nv_bfloat16* brow = Bp + (size_t)(bn + tid) * K3 + kc;
        uint32_t bboff = bb + (uint32_t)(tid << 7);
        #pragma unroll
        for (int c16 = 0; c16 < 8; ++c16)  // B: 256 rows x 8 c16, row=tid
            CP_ASYNC16(bboff + (uint32_t)((c16 ^ (tid & 7)) << 4), brow + (c16 << 3));
        CP_COMMIT();
    };

    load_chunk(0, 0);

    for (int kt = 0; kt < NT; ++kt) {
        const int buf = kt & 1;
        if (kt + 1 < NT) { load_chunk(kt + 1, buf ^ 1); CP_WAIT1(); }
        else             { CP_WAIT0(); }
        __syncthreads();

        const uint32_t ab = base + buf * STAGE;
        const uint32_t bb = ab + 16384;
        const int t4 = lane >> 3;

        #pragma unroll
        for (int ks = 0; ks < 4; ++ks) {
            uint32_t Af[4][4];
            #pragma unroll
            for (int mt = 0; mt < 4; ++mt) {
                int row = wm + mt * 16 + ((t4 & 1) << 3) + (lane & 7);
                int c16 = ks * 2 + (t4 >> 1);
                uint32_t addr = ab + (uint32_t)(row << 7)
                              + (uint32_t)((c16 ^ (row & 7)) << 4);
                ldsm_x4(Af[mt][0], Af[mt][1], Af[mt][2], Af[mt][3], addr);
            }
            uint32_t Bf[4][4];   // 4 n16 groups: [b0 n0-7][b1 n0-7][b0 n8-15][b1 n8-15]
            #pragma unroll
            for (int gt = 0; gt < 4; ++gt) {
                int row = wn + gt * 16 + ((t4 >> 1) << 3) + (lane & 7);
                int c16 = ks * 2 + (t4 & 1);
                uint32_t addr = bb + (uint32_t)(row << 7)
                              + (uint32_t)((c16 ^ (row & 7)) << 4);
                ldsm_x4(Bf[gt][0], Bf[gt][1], Bf[gt][2], Bf[gt][3], addr);
            }
            #pragma unroll
            for (int mt = 0; mt < 4; ++mt)
                #pragma unroll
                for (int ng = 0; ng < 8; ++ng) {
                    const uint32_t* bg = Bf[ng >> 1];
                    mma_bf16(acc[mt][ng],
                             Af[mt][0], Af[mt][1], Af[mt][2], Af[mt][3],
                             bg[(ng & 1) * 2], bg[(ng & 1) * 2 + 1]);
                }
        }
        __syncthreads();
    }

    // ---------------- epilogue (operand smem reused as slab) ----------------
    const int qr = lane >> 2;          // 0..7
    const int qc = (lane & 3) << 1;    // 0,2,4,6

    if (EPI == 0) {
        float* slab = reinterpret_cast<float*>(sm);   // [m][n] pitch 264
        #pragma unroll
        for (int mt = 0; mt < 4; ++mt)
            #pragma unroll
            for (int ng = 0; ng < 8; ++ng) {
                int m = wm + mt * 16 + qr;
                int n = wn + ng * 8 + qc;
                float* p0 = slab + (size_t)m * 264 + n;
                p0[0] = acc[mt][ng][0] * scale;
                p0[1] = acc[mt][ng][1] * scale;
                float* p1 = p0 + 8 * 264;
                p1[0] = acc[mt][ng][2] * scale;
                p1[1] = acc[mt][ng][3] * scale;
            }
        __syncthreads();
        float* C = Cg + blockIdx.z * sOut;
        #pragma unroll
        for (int it = 0; it < 32; ++it) {
            int idx = tid + (it << 8);
            int r = idx >> 6, c = (idx & 63) << 2;
            float4 v = *reinterpret_cast<float4*>(slab + (size_t)r * 264 + c);
            *reinterpret_cast<float4*>(C + (size_t)(bm + r) * ldc + bn + c) = v;
        }
    } else {
        float* slab = reinterpret_cast<float*>(sm);   // [n][m] pitch 132
        #pragma unroll
        for (int mt = 0; mt < 4; ++mt)
            #pragma unroll
            for (int ng = 0; ng < 8; ++ng) {
                int m = wm + mt * 16 + qr;
                int n = wn + ng * 8 + qc;
                slab[(size_t)n * 132 + m]           = acc[mt][ng][0];
                slab[(size_t)(n + 1) * 132 + m]     = acc[mt][ng][1];
                slab[(size_t)n * 132 + m + 8]       = acc[mt][ng][2];
                slab[(size_t)(n + 1) * 132 + m + 8] = acc[mt][ng][3];
            }
        __syncthreads();
        __nv_bfloat16* T = Tg + blockIdx.z * sOut;
        #pragma unroll
        for (int it = 0; it < 32; ++it) {
            int idx = tid + (it << 8);          // 8192 (n, m-chunk4) pairs
            int n = idx >> 5, mc = (idx & 31) << 2;
            float4 v = *reinterpret_cast<float4*>(slab + (size_t)n * 132 + mc);
            float xs[4] = {v.x, v.y, v.z, v.w};
            __align__(8) __nv_bfloat16 h[4], l[4];
            #pragma unroll
            for (int i = 0; i < 4; ++i) {
                h[i] = __float2bfloat16(xs[i]);
                l[i] = __float2bfloat16(xs[i] - __bfloat162float(h[i]));
            }
            __nv_bfloat16* dst = T + (size_t)(bn + n) * K3A + bm + mc;
            *reinterpret_cast<uint2*>(dst)           = *reinterpret_cast<uint2*>(h);
            *reinterpret_cast<uint2*>(dst + LQ_)     = *reinterpret_cast<uint2*>(l);
            *reinterpret_cast<uint2*>(dst + 2 * LQ_) = *reinterpret_cast<uint2*>(h);
        }
    }
}

// ------------- fp32 -> bf16 hi/lo split, row-wise (no transpose) -------------
// ROLE 0: [h|h|l] (A-role).  ROLE 1: [h|l|h] (B-role).  Row pitch 3*Dn.
template<int ROLE>
__global__ void __launch_bounds__(256) split_rows(
    const float* __restrict__ in, __nv_bfloat16* __restrict__ out, int Dn)
{
    size_t idx = (size_t)blockIdx.x * 256 + threadIdx.x;     // one float4
    size_t row = idx / (size_t)(Dn >> 2);
    int    c   = (int)(idx % (size_t)(Dn >> 2)) << 2;
    float4 v = *reinterpret_cast<const float4*>(in + row * Dn + c);
    float xs[4] = {v.x, v.y, v.z, v.w};
    __align__(8) __nv_bfloat16 h[4], l[4];
    #pragma unroll
    for (int i = 0; i < 4; ++i) {
        h[i] = __float2bfloat16(xs[i]);
        l[i] = __float2bfloat16(xs[i] - __bfloat162float(h[i]));
    }
    __nv_bfloat16* o = out + row * (size_t)(3 * Dn) + c;
    *reinterpret_cast<uint2*>(o)                          = *reinterpret_cast<uint2*>(h);
    *reinterpret_cast<uint2*>(o + (ROLE ? 2 * Dn : Dn))   = *reinterpret_cast<uint2*>(h);
    *reinterpret_cast<uint2*>(o + (ROLE ? Dn : 2 * Dn))   = *reinterpret_cast<uint2*>(l);
}

// ------------- transpose + split: in [B][R][Cd] fp32 -> out [B][Cd][3R] bf16 -------------
template<int ROLE>
__global__ void __launch_bounds__(256) tsplit(
    const float* __restrict__ in, __nv_bfloat16* __restrict__ out, int R, int Cd)
{
    __shared__ float tile[32][33];
    const int r0 = blockIdx.x * 32, c0 = blockIdx.y * 32;
    const float* ip = in + (size_t)blockIdx.z * R * Cd;
    __nv_bfloat16* op = out + (size_t)blockIdx.z * Cd * 3 * R;
    const int tx = threadIdx.x & 31, ty = threadIdx.x >> 5;
    #pragma unroll
    for (int j = 0; j < 4; ++j)
        tile[ty + j * 8][tx] = ip[(size_t)(r0 + ty + j * 8) * Cd + c0 + tx];
    __syncthreads();
    #pragma unroll
    for (int j = 0; j < 4; ++j) {
        int cc = ty + j * 8;
        float x = tile[tx][cc];
        __nv_bfloat16 h = __float2bfloat16(x);
        __nv_bfloat16 l = __float2bfloat16(x - __bfloat162float(h));
        __nv_bfloat16* o = op + (size_t)(c0 + cc) * 3 * R + r0 + tx;
        o[0]                  = h;
        o[ROLE ? 2 * R : R]   = h;
        o[ROLE ? R : 2 * R]   = l;
    }
}

// ------------- masked softmax + A-role split of aw -------------
__global__ void __launch_bounds__(256) softmax_mask_split(
    float* __restrict__ aw, const int* __restrict__ mask, __nv_bfloat16* __restrict__ aws)
{
    const int row = blockIdx.x;
    const int b   = row >> 11;
    float*         rp = aw   + (size_t)row * S_;
    __nv_bfloat16* ap = aws  + (size_t)row * K3A;
    const int*     mp = mask + (size_t)b   * S_;
    const int t = threadIdx.x;
    const float NEG_INF = __int_as_float(0xff800000);

    float v[8]; int mk[8];
    float mx = NEG_INF;
    #pragma unroll
    for (int i = 0; i < 8; ++i) {
        int j = t + (i << 8);
        mk[i] = mp[j];
        float s = rp[j];
        v[i] = mk[i] ? s : NEG_INF;
        mx = fmaxf(mx, v[i]);
    }
    __shared__ float smax[8], ssum[8];
    #pragma unroll
    for (int off = 16; off > 0; off >>= 1)
        mx = fmaxf(mx, __shfl_xor_sync(0xffffffffu, mx, off));
    if ((t & 31) == 0) smax[t >> 5] = mx;
    __syncthreads();
    float rmax = smax[0];
    #pragma unroll
    for (int i = 1; i < 8; ++i) rmax = fmaxf(rmax, smax[i]);

    float e[8], sum = 0.f;
    #pragma unroll
    for (int i = 0; i < 8; ++i) {
        e[i] = mk[i] ? __expf(v[i] - rmax) : 0.f;
        sum += e[i];
    }
    #pragma unroll
    for (int off = 16; off > 0; off >>= 1)
        sum += __shfl_xor_sync(0xffffffffu, sum, off);
    if ((t & 31) == 0) ssum[t >> 5] = sum;
    __syncthreads();
    float rsum = 0.f;
    #pragma unroll
    for (int i = 0; i < 8; ++i) rsum += ssum[i];
    const float inv = 1.f / rsum;

    #pragma unroll
    for (int i = 0; i < 8; ++i) {
        int j = t + (i << 8);
        float p = e[i] * inv;
        rp[j] = p;
        __nv_bfloat16 h = __float2bfloat16(p);
        __nv_bfloat16 l = __float2bfloat16(p - __bfloat162float(h));
        ap[j]           = h;      // A-role [h | h | l]
        ap[S_ + j]      = h;
        ap[2 * S_ + j]  = l;
    }
}

extern "C" void kernel_launch(void* const* d_in, const int* in_sizes, int n_in,
                              void* d_out, int out_size)
{
    const float* q    = (const float*)d_in[0];
    const float* kk   = (const float*)d_in[1];
    const float* v    = (const float*)d_in[2];
    const int*   mask = (const int*)  d_in[3];

    float* out = (float*)d_out;                       // output [B,S,D]
    float* aw  = out + (size_t)B_ * S_ * D_;          // attention_weights [B,LQ,S]

    void* p;
    cudaGetSymbolAddress(&p, g_qs);   __nv_bfloat16* qs   = (__nv_bfloat16*)p;
    cudaGetSymbolAddress(&p, g_ks);   __nv_bfloat16* ks   = (__nv_bfloat16*)p;
    cudaGetSymbolAddress(&p, g_vts);  __nv_bfloat16* vts  = (__nv_bfloat16*)p;
    cudaGetSymbolAddress(&p, g_aws);  __nv_bfloat16* aws  = (__nv_bfloat16*)p;
    cudaGetSymbolAddress(&p, g_awts); __nv_bfloat16* awts = (__nv_bfloat16*)p;
    cudaGetSymbolAddress(&p, g_o1ts); __nv_bfloat16* o1ts = (__nv_bfloat16*)p;

    cudaFuncSetAttribute(gemm_mma<0>, cudaFuncAttributeMaxDynamicSharedMemorySize, SMEM_SZ);
    cudaFuncSetAttribute(gemm_mma<1>, cudaFuncAttributeMaxDynamicSharedMemorySize, SMEM_SZ);

    const int nsplit = (int)(((size_t)B_ * LQ_ * D_ / 4) / 256);   // 32768 blocks

    // 0a) Q split (A-role), K split (B-role)
    split_rows<0><<<nsplit, 256>>>(q,  qs, D_);
    split_rows<1><<<nsplit, 256>>>(kk, ks, D_);
    // 0b) V^T split (B-role): in [S,D] -> out [D,3S]
    tsplit<1><<<dim3(S_ / 32, D_ / 32, B_), 256>>>(v, vts, S_, D_);

    // 1) scores = Q @ K^T / 32 -> aw (fp32)
    gemm_mma<0><<<dim3(S_ / 256, LQ_ / 128, B_), 256, SMEM_SZ>>>(
        qs, ks, aw, nullptr, K3QK, S_,
        (size_t)LQ_ * K3QK, (size_t)S_ * K3QK, (size_t)LQ_ * S_, 0.03125f);

    // 2) masked softmax in place + aw split (A-role)
    softmax_mask_split<<<B_ * LQ_, 256>>>(aw, mask, aws);

    // 2b) aw^T split (A-role): in [LQ,S] -> out [S,3LQ]
    tsplit<0><<<dim3(LQ_ / 32, S_ / 32, B_), 256>>>(aw, awts, LQ_, S_);

    // 3) out1 = aw @ V  ->  o1ts (bf16 split-transposed, B-role)
    gemm_mma<1><<<dim3(D_ / 256, LQ_ / 128, B_), 256, SMEM_SZ>>>(
        aws, vts, nullptr, o1ts, K3A, 0,
        (size_t)LQ_ * K3A, (size_t)D_ * K3A, (size_t)D_ * K3A, 1.0f);

    // 4) output = aw^T @ out1 -> out (fp32)
    gemm_mma<0><<<dim3(D_ / 256, S_ / 128, B_), 256, SMEM_SZ>>>(
        awts, o1ts, out, nullptr, K3A, D_,
        (size_t)S_ * K3A, (size_t)D_ * K3A, (size_t)S_ * D_, 1.0f);
}

// round 9
// speedup vs baseline: 1.2774x; 1.2774x over previous
#include <cuda_runtime.h>
#include <cuda_bf16.h>
#include <cstdint>

#define B_  16
#define LQ_ 2048
#define S_  2048
#define D_  1024
#define K3QK 3072    // 3*D
#define K3A  6144    // 3*S == 3*LQ

// ------------- scratch (__device__ globals = allocation-guard-safe) -------------
static __device__ __nv_bfloat16 g_qs  [(size_t)B_ * LQ_ * K3QK];  // Q split  A-role [h|h|l]
static __device__ __nv_bfloat16 g_ks  [(size_t)B_ * S_  * K3QK];  // K split  B-role [h|l|h]
static __device__ __nv_bfloat16 g_vts [(size_t)B_ * D_  * K3A];   // V^T split B-role
static __device__ __nv_bfloat16 g_aws [(size_t)B_ * LQ_ * K3A];   // aw split  A-role
static __device__ __nv_bfloat16 g_awts[(size_t)B_ * S_  * K3A];   // aw^T split A-role
static __device__ __nv_bfloat16 g_o1ts[(size_t)B_ * D_  * K3A];   // out1^T split B-role

// ------------- PTX helpers (sm_100 baseline ISA: cp.async/ldmatrix/mma.sync) ----
__device__ __forceinline__ uint32_t smem_u32(const void* p) {
    uint32_t a;
    asm("{ .reg .u64 t; cvta.to.shared.u64 t, %1; cvt.u32.u64 %0, t; }" : "=r"(a) : "l"(p));
    return a;
}
#define CP_ASYNC16(dst, src) \
    asm volatile("cp.async.cg.shared.global [%0], [%1], 16;" :: "r"(dst), "l"(src) : "memory")
#define CP_COMMIT() asm volatile("cp.async.commit_group;" ::: "memory")
#define CP_WAIT1()  asm volatile("cp.async.wait_group 1;" ::: "memory")
#define CP_WAIT0()  asm volatile("cp.async.wait_group 0;" ::: "memory")

__device__ __forceinline__ void ldsm_x4(uint32_t& r0, uint32_t& r1, uint32_t& r2,
                                        uint32_t& r3, uint32_t addr) {
    asm volatile("ldmatrix.sync.aligned.m8n8.x4.shared.b16 {%0,%1,%2,%3}, [%4];"
                 : "=r"(r0), "=r"(r1), "=r"(r2), "=r"(r3) : "r"(addr));
}
__device__ __forceinline__ void mma_bf16(float* c, uint32_t a0, uint32_t a1,
                                         uint32_t a2, uint32_t a3,
                                         uint32_t b0, uint32_t b1) {
    asm volatile(
        "mma.sync.aligned.m16n8k16.row.col.f32.bf16.bf16.f32 "
        "{%0,%1,%2,%3}, {%4,%5,%6,%7}, {%8,%9}, {%0,%1,%2,%3};"
        : "+f"(c[0]), "+f"(c[1]), "+f"(c[2]), "+f"(c[3])
        : "r"(a0), "r"(a1), "r"(a2), "r"(a3), "r"(b0), "r"(b1));
}

// SMEM: 1KB align pad + 3 stages x 32KB (A 16KB + B 16KB). Epilogue slab
// (128 x 132 fp32 = 67.6KB) reuses the stage area. 2 CTAs/SM: 194KB < 227KB.
static constexpr int STAGE   = 32768;
static constexpr int SMEM_SZ = 1024 + 3 * STAGE;

// ------------- mma.sync GEMM: C[M,N] = scale * A[M,K3] @ B[N,K3]^T -------------
// CTA tile 128x128, 8 warps (2m x 4n), warp tile 64x32, K chunks of 64 bf16 with
// SW128 xor-swizzle; 3-stage cp.async ring, ONE __syncthreads per chunk.
// EPI=0: fp32 row-major C (ldc, scale). EPI=1: bf16 [h|l|h] transposed into Tg
//        with row pitch K3A (B-role split of C^T).
template<int EPI>
__global__ void __launch_bounds__(256, 2) gemm_mma(
    const __nv_bfloat16* __restrict__ Ag,
    const __nv_bfloat16* __restrict__ Bg,
    float* __restrict__ Cg, __nv_bfloat16* __restrict__ Tg,
    int K3, int ldc, size_t sA, size_t sB, size_t sOut, float scale)
{
    extern __shared__ char dsm[];
    const uint32_t raw  = smem_u32(dsm);
    const uint32_t base = (raw + 1023u) & ~1023u;
    char* sm = dsm + (base - raw);

    const int tid  = threadIdx.x;
    const int wid  = tid >> 5;
    const int lane = tid & 31;
    const int bm   = blockIdx.y * 128;
    const int bn   = blockIdx.x * 128;
    const __nv_bfloat16* A  = Ag + blockIdx.z * sA;
    const __nv_bfloat16* Bp = Bg + blockIdx.z * sB;

    const int wm = (wid & 1) * 64;         // warp m-offset
    const int wn = (wid >> 1) * 32;        // warp n-offset

    float acc[4][4][4];
    #pragma unroll
    for (int i = 0; i < 4; ++i)
        #pragma unroll
        for (int j = 0; j < 4; ++j)
            #pragma unroll
            for (int r = 0; r < 4; ++r) acc[i][j][r] = 0.f;

    const int lr  = tid >> 1;              // load row 0..127
    const int lc0 = (tid & 1) << 2;        // chunk-of-16B base: 0 or 4

    const int NT = K3 >> 6;

    auto load_chunk = [&](int kt) {
        const int kc = kt << 6;
        const uint32_t ab = base + (kt % 3) * STAGE;
        const uint32_t bb = ab + 16384;
        const __nv_bfloat16* arow = A  + (size_t)(bm + lr) * K3 + kc;
        const __nv_bfloat16* brow = Bp + (size_t)(bn + lr) * K3 + kc;
        #pragma unroll
        for (int c = 0; c < 4; ++c) {
            int c16 = lc0 + c;
            uint32_t sw = (uint32_t)((c16 ^ (lr & 7)) << 4);
            CP_ASYNC16(ab + (uint32_t)(lr << 7) + sw, arow + (c16 << 3));
            CP_ASYNC16(bb + (uint32_t)(lr << 7) + sw, brow + (c16 << 3));
        }
        CP_COMMIT();
    };

    load_chunk(0);
    load_chunk(1);

    for (int kt = 0; kt < NT; ++kt) {
        if (kt + 1 < NT) CP_WAIT1();       // retire group kt (kt+1 may fly)
        else             CP_WAIT0();
        __syncthreads();                   // all writers done, all readers of
                                           // stage (kt+2)%3 are past chunk kt-1
        if (kt + 2 < NT) load_chunk(kt + 2);

        const uint32_t ab = base + (kt % 3) * STAGE;
        const uint32_t bb = ab + 16384;
        const int t4 = lane >> 3;

        #pragma unroll
        for (int ks = 0; ks < 4; ++ks) {
            uint32_t Af[4][4];
            #pragma unroll
            for (int mt = 0; mt < 4; ++mt) {
                int row = wm + mt * 16 + ((t4 & 1) << 3) + (lane & 7);
                int c16 = ks * 2 + (t4 >> 1);
                uint32_t addr = ab + (uint32_t)(row << 7)
                              + (uint32_t)((c16 ^ (row & 7)) << 4);
                ldsm_x4(Af[mt][0], Af[mt][1], Af[mt][2], Af[mt][3], addr);
            }
            uint32_t Bf[2][4];   // 2 n16 groups: [b0 n0-7][b1 n0-7][b0 n8-15][b1 n8-15]
            #pragma unroll
            for (int gt = 0; gt < 2; ++gt) {
                int row = wn + gt * 16 + ((t4 >> 1) << 3) + (lane & 7);
                int c16 = ks * 2 + (t4 & 1);
                uint32_t addr = bb + (uint32_t)(row << 7)
                              + (uint32_t)((c16 ^ (row & 7)) << 4);
                ldsm_x4(Bf[gt][0], Bf[gt][1], Bf[gt][2], Bf[gt][3], addr);
            }
            #pragma unroll
            for (int mt = 0; mt < 4; ++mt)
                #pragma unroll
                for (int ng = 0; ng < 4; ++ng) {
                    const uint32_t* bg = Bf[ng >> 1];
                    mma_bf16(acc[mt][ng],
                             Af[mt][0], Af[mt][1], Af[mt][2], Af[mt][3],
                             bg[(ng & 1) * 2], bg[(ng & 1) * 2 + 1]);
                }
        }
    }
    __syncthreads();                       // before reusing stages as slab

    // ---------------- epilogue (operand smem reused as slab) ----------------
    const int qr = lane >> 2;          // 0..7
    const int qc = (lane & 3) << 1;    // 0,2,4,6

    if (EPI == 0) {
        float* slab = reinterpret_cast<float*>(sm);   // [m][n] pitch 132
        #pragma unroll
        for (int mt = 0; mt < 4; ++mt)
            #pragma unroll
            for (int ng = 0; ng < 4; ++ng) {
                int m = wm + mt * 16 + qr;
                int n = wn + ng * 8 + qc;
                float* p0 = slab + (size_t)m * 132 + n;
                p0[0] = acc[mt][ng][0] * scale;
                p0[1] = acc[mt][ng][1] * scale;
                float* p1 = p0 + 8 * 132;
                p1[0] = acc[mt][ng][2] * scale;
                p1[1] = acc[mt][ng][3] * scale;
            }
        __syncthreads();
        float* C = Cg + blockIdx.z * sOut;
        #pragma unroll
        for (int it = 0; it < 16; ++it) {
            int idx = tid + (it << 8);
            int r = idx >> 5, c = (idx & 31) << 2;
            float4 v = *reinterpret_cast<float4*>(slab + (size_t)r * 132 + c);
            *reinterpret_cast<float4*>(C + (size_t)(bm + r) * ldc + bn + c) = v;
        }
    } else {
        float* slab = reinterpret_cast<float*>(sm);   // [n][m] pitch 132
        #pragma unroll
        for (int mt = 0; mt < 4; ++mt)
            #pragma unroll
            for (int ng = 0; ng < 4; ++ng) {
                int m = wm + mt * 16 + qr;
                int n = wn + ng * 8 + qc;
                slab[(size_t)n * 132 + m]           = acc[mt][ng][0];
                slab[(size_t)(n + 1) * 132 + m]     = acc[mt][ng][1];
                slab[(size_t)n * 132 + m + 8]       = acc[mt][ng][2];
                slab[(size_t)(n + 1) * 132 + m + 8] = acc[mt][ng][3];
            }
        __syncthreads();
        __nv_bfloat16* T = Tg + blockIdx.z * sOut;
        #pragma unroll
        for (int it = 0; it < 16; ++it) {
            int idx = tid + (it << 8);          // 4096 (n, m-chunk4) pairs
            int n = idx >> 5, mc = (idx & 31) << 2;
            float4 v = *reinterpret_cast<float4*>(slab + (size_t)n * 132 + mc);
            float xs[4] = {v.x, v.y, v.z, v.w};
            __align__(8) __nv_bfloat16 h[4], l[4];
            #pragma unroll
            for (int i = 0; i < 4; ++i) {
                h[i] = __float2bfloat16(xs[i]);
                l[i] = __float2bfloat16(xs[i] - __bfloat162float(h[i]));
            }
            __nv_bfloat16* dst = T + (size_t)(bn + n) * K3A + bm + mc;
            *reinterpret_cast<uint2*>(dst)           = *reinterpret_cast<uint2*>(h);
            *reinterpret_cast<uint2*>(dst + LQ_)     = *reinterpret_cast<uint2*>(l);
            *reinterpret_cast<uint2*>(dst + 2 * LQ_) = *reinterpret_cast<uint2*>(h);
        }
    }
}

// ------------- fp32 -> bf16 hi/lo split, row-wise (no transpose) -------------
// ROLE 0: [h|h|l] (A-role).  ROLE 1: [h|l|h] (B-role).  Row pitch 3*Dn.
template<int ROLE>
__global__ void __launch_bounds__(256) split_rows(
    const float* __restrict__ in, __nv_bfloat16* __restrict__ out, int Dn)
{
    size_t idx = (size_t)blockIdx.x * 256 + threadIdx.x;     // one float4
    size_t row = idx / (size_t)(Dn >> 2);
    int    c   = (int)(idx % (size_t)(Dn >> 2)) << 2;
    float4 v = *reinterpret_cast<const float4*>(in + row * Dn + c);
    float xs[4] = {v.x, v.y, v.z, v.w};
    __align__(8) __nv_bfloat16 h[4], l[4];
    #pragma unroll
    for (int i = 0; i < 4; ++i) {
        h[i] = __float2bfloat16(xs[i]);
        l[i] = __float2bfloat16(xs[i] - __bfloat162float(h[i]));
    }
    __nv_bfloat16* o = out + row * (size_t)(3 * Dn) + c;
    *reinterpret_cast<uint2*>(o)                          = *reinterpret_cast<uint2*>(h);
    *reinterpret_cast<uint2*>(o + (ROLE ? 2 * Dn : Dn))   = *reinterpret_cast<uint2*>(h);
    *reinterpret_cast<uint2*>(o + (ROLE ? Dn : 2 * Dn))   = *reinterpret_cast<uint2*>(l);
}

// ------------- transpose + split: in [B][R][Cd] fp32 -> out [B][Cd][3R] bf16 -------------
template<int ROLE>
__global__ void __launch_bounds__(256) tsplit(
    const float* __restrict__ in, __nv_bfloat16* __restrict__ out, int R, int Cd)
{
    __shared__ float tile[32][33];
    const int r0 = blockIdx.x * 32, c0 = blockIdx.y * 32;
    const float* ip = in + (size_t)blockIdx.z * R * Cd;
    __nv_bfloat16* op = out + (size_t)blockIdx.z * Cd * 3 * R;
    const int tx = threadIdx.x & 31, ty = threadIdx.x >> 5;
    #pragma unroll
    for (int j = 0; j < 4; ++j)
        tile[ty + j * 8][tx] = ip[(size_t)(r0 + ty + j * 8) * Cd + c0 + tx];
    __syncthreads();
    #pragma unroll
    for (int j = 0; j < 4; ++j) {
        int cc = ty + j * 8;
        float x = tile[tx][cc];
        __nv_bfloat16 h = __float2bfloat16(x);
        __nv_bfloat16 l = __float2bfloat16(x - __bfloat162float(h));
        __nv_bfloat16* o = op + (size_t)(c0 + cc) * 3 * R + r0 + tx;
        o[0]                  = h;
        o[ROLE ? 2 * R : R]   = h;
        o[ROLE ? R : 2 * R]   = l;
    }
}

// ------------- masked softmax + A-role split of aw -------------
__global__ void __launch_bounds__(256) softmax_mask_split(
    float* __restrict__ aw, const int* __restrict__ mask, __nv_bfloat16* __restrict__ aws)
{
    const int row = blockIdx.x;
    const int b   = row >> 11;
    float*         rp = aw   + (size_t)row * S_;
    __nv_bfloat16* ap = aws  + (size_t)row * K3A;
    const int*     mp = mask + (size_t)b   * S_;
    const int t = threadIdx.x;
    const float NEG_INF = __int_as_float(0xff800000);

    float v[8]; int mk[8];
    float mx = NEG_INF;
    #pragma unroll
    for (int i = 0; i < 8; ++i) {
        int j = t + (i << 8);
        mk[i] = mp[j];
        float s = rp[j];
        v[i] = mk[i] ? s : NEG_INF;
        mx = fmaxf(mx, v[i]);
    }
    __shared__ float smax[8], ssum[8];
    #pragma unroll
    for (int off = 16; off > 0; off >>= 1)
        mx = fmaxf(mx, __shfl_xor_sync(0xffffffffu, mx, off));
    if ((t & 31) == 0) smax[t >> 5] = mx;
    __syncthreads();
    float rmax = smax[0];
    #pragma unroll
    for (int i = 1; i < 8; ++i) rmax = fmaxf(rmax, smax[i]);

    float e[8], sum = 0.f;
    #pragma unroll
    for (int i = 0; i < 8; ++i) {
        e[i] = mk[i] ? __expf(v[i] - rmax) : 0.f;
        sum += e[i];
    }
    #pragma unroll
    for (int off = 16; off > 0; off >>= 1)
        sum += __shfl_xor_sync(0xffffffffu, sum, off);
    if ((t & 31) == 0) ssum[t >> 5] = sum;
    __syncthreads();
    float rsum = 0.f;
    #pragma unroll
    for (int i = 0; i < 8; ++i) rsum += ssum[i];
    const float inv = 1.f / rsum;

    #pragma unroll
    for (int i = 0; i < 8; ++i) {
        int j = t + (i << 8);
        float p = e[i] * inv;
        rp[j] = p;
        __nv_bfloat16 h = __float2bfloat16(p);
        __nv_bfloat16 l = __float2bfloat16(p - __bfloat162float(h));
        ap[j]           = h;      // A-role [h | h | l]
        ap[S_ + j]      = h;
        ap[2 * S_ + j]  = l;
    }
}

extern "C" void kernel_launch(void* const* d_in, const int* in_sizes, int n_in,
                              void* d_out, int out_size)
{
    const float* q    = (const float*)d_in[0];
    const float* kk   = (const float*)d_in[1];
    const float* v    = (const float*)d_in[2];
    const int*   mask = (const int*)  d_in[3];

    float* out = (float*)d_out;                       // output [B,S,D]
    float* aw  = out + (size_t)B_ * S_ * D_;          // attention_weights [B,LQ,S]

    void* p;
    cudaGetSymbolAddress(&p, g_qs);   __nv_bfloat16* qs   = (__nv_bfloat16*)p;
    cudaGetSymbolAddress(&p, g_ks);   __nv_bfloat16* ks   = (__nv_bfloat16*)p;
    cudaGetSymbolAddress(&p, g_vts);  __nv_bfloat16* vts  = (__nv_bfloat16*)p;
    cudaGetSymbolAddress(&p, g_aws);  __nv_bfloat16* aws  = (__nv_bfloat16*)p;
    cudaGetSymbolAddress(&p, g_awts); __nv_bfloat16* awts = (__nv_bfloat16*)p;
    cudaGetSymbolAddress(&p, g_o1ts); __nv_bfloat16* o1ts = (__nv_bfloat16*)p;

    cudaFuncSetAttribute(gemm_mma<0>, cudaFuncAttributeMaxDynamicSharedMemorySize, SMEM_SZ);
    cudaFuncSetAttribute(gemm_mma<1>, cudaFuncAttributeMaxDynamicSharedMemorySize, SMEM_SZ);

    const int nsplit = (int)(((size_t)B_ * LQ_ * D_ / 4) / 256);   // 32768 blocks

    // 0a) Q split (A-role), K split (B-role)
    split_rows<0><<<nsplit, 256>>>(q,  qs, D_);
    split_rows<1><<<nsplit, 256>>>(kk, ks, D_);
    // 0b) V^T split (B-role): in [S,D] -> out [D,3S]
    tsplit<1><<<dim3(S_ / 32, D_ / 32, B_), 256>>>(v, vts, S_, D_);

    // 1) scores = Q @ K^T / 32 -> aw (fp32)
    gemm_mma<0><<<dim3(S_ / 128, LQ_ / 128, B_), 256, SMEM_SZ>>>(
        qs, ks, aw, nullptr, K3QK, S_,
        (size_t)LQ_ * K3QK, (size_t)S_ * K3QK, (size_t)LQ_ * S_, 0.03125f);

    // 2) masked softmax in place + aw split (A-role)
    softmax_mask_split<<<B_ * LQ_, 256>>>(aw, mask, aws);

    // 2b) aw^T split (A-role): in [LQ,S] -> out [S,3LQ]
    tsplit<0><<<dim3(LQ_ / 32, S_ / 32, B_), 256>>>(aw, awts, LQ_, S_);

    // 3) out1 = aw @ V  ->  o1ts (bf16 split-transposed, B-role)
    gemm_mma<1><<<dim3(D_ / 128, LQ_ / 128, B_), 256, SMEM_SZ>>>(
        aws, vts, nullptr, o1ts, K3A, 0,
        (size_t)LQ_ * K3A, (size_t)D_ * K3A, (size_t)D_ * K3A, 1.0f);

    // 4) output = aw^T @ out1 -> out (fp32)
    gemm_mma<0><<<dim3(D_ / 128, S_ / 128, B_), 256, SMEM_SZ>>>(
        awts, o1ts, out, nullptr, K3A, D_,
        (size_t)S_ * K3A, (size_t)D_ * K3A, (size_t)S_ * D_, 1.0f);
}

// round 10
// speedup vs baseline: 2.1114x; 1.6529x over previous
#include <cuda_runtime.h>
#include <cuda_bf16.h>
#include <cstdint>

#define B_  16
#define LQ_ 2048
#define S_  2048
#define D_  1024
#define K3QK 3072    // 3*D
#define K3A  6144    // 3*S == 3*LQ

// ------------- scratch (__device__ globals = allocation-guard-safe) -------------
static __device__ __nv_bfloat16 g_qs  [(size_t)B_ * LQ_ * K3QK];  // Q split  A-role [h|h|l]
static __device__ __nv_bfloat16 g_ks  [(size_t)B_ * S_  * K3QK];  // Kc split B-role [h|l|h] (compacted rows)
static __device__ __nv_bfloat16 g_vts [(size_t)B_ * D_  * K3A];   // Vc^T split B-role (compact K)
static __device__ __nv_bfloat16 g_aws [(size_t)B_ * LQ_ * K3A];   // awc split A-role (compact K)
static __device__ __nv_bfloat16 g_awts[(size_t)B_ * S_  * K3A];   // awc^T split A-role (compact M rows)
static __device__ __nv_bfloat16 g_o1ts[(size_t)B_ * D_  * K3A];   // out1^T split B-role (full)
static __device__ float         g_awc [(size_t)B_ * LQ_ * S_];    // compacted scores / probs fp32
static __device__ int           g_pos [B_ * S_];
static __device__ int           g_idx [B_ * S_];
static __device__ int           g_scnt[B_];
static __device__ int           g_sp  [B_];

// ------------- PTX helpers -------------
__device__ __forceinline__ uint32_t smem_u32(const void* p) {
    uint32_t a;
    asm("{ .reg .u64 t; cvta.to.shared.u64 t, %1; cvt.u32.u64 %0, t; }" : "=r"(a) : "l"(p));
    return a;
}
#define CP_ASYNC16(dst, src) \
    asm volatile("cp.async.cg.shared.global [%0], [%1], 16;" :: "r"(dst), "l"(src) : "memory")
#define CP_COMMIT() asm volatile("cp.async.commit_group;" ::: "memory")
#define CP_WAIT1()  asm volatile("cp.async.wait_group 1;" ::: "memory")
#define CP_WAIT0()  asm volatile("cp.async.wait_group 0;" ::: "memory")

__device__ __forceinline__ void ldsm_x4(uint32_t& r0, uint32_t& r1, uint32_t& r2,
                                        uint32_t& r3, uint32_t addr) {
    asm volatile("ldmatrix.sync.aligned.m8n8.x4.shared.b16 {%0,%1,%2,%3}, [%4];"
                 : "=r"(r0), "=r"(r1), "=r"(r2), "=r"(r3) : "r"(addr));
}
__device__ __forceinline__ void mma_bf16(float* c, uint32_t a0, uint32_t a1,
                                         uint32_t a2, uint32_t a3,
                                         uint32_t b0, uint32_t b1) {
    asm volatile(
        "mma.sync.aligned.m16n8k16.row.col.f32.bf16.bf16.f32 "
        "{%0,%1,%2,%3}, {%4,%5,%6,%7}, {%8,%9}, {%0,%1,%2,%3};"
        : "+f"(c[0]), "+f"(c[1]), "+f"(c[2]), "+f"(c[3])
        : "r"(a0), "r"(a1), "r"(a2), "r"(a3), "r"(b0), "r"(b1));
}

static constexpr int STAGE   = 32768;
static constexpr int SMEM_SZ = 1024 + 3 * STAGE;

// ------------- mma.sync GEMM: C[M,N] = scale * A[M,K] @ B[N,K]^T -------------
// CTA 128x128, 8 warps 64x32, 64-K chunks, SW128 xor swizzle, 3-stage cp.async ring.
// MODE 0 (G1): N-compact (exit bn>=SP), K extent = ld, fp32 C at ldc.
// MODE 1 (G2): K extent = 3*SP (runtime), pitch ld; bf16 [h|l|h] transposed epi into Tg.
// MODE 2 (G3): M-compact (exit bm>=SP), K = ld; fp32 rows scattered via idx (r < Sc).
template<int MODE>
__global__ void __launch_bounds__(256, 2) gemm_mma(
    const __nv_bfloat16* __restrict__ Ag,
    const __nv_bfloat16* __restrict__ Bg,
    float* __restrict__ Cg, __nv_bfloat16* __restrict__ Tg,
    int ld, int ldc, size_t sA, size_t sB, size_t sOut, float scale,
    const int* __restrict__ scnt, const int* __restrict__ sptab,
    const int* __restrict__ idxb)
{
    const int bz = blockIdx.z;
    const int SP = sptab[bz];
    const int bm = blockIdx.y * 128;
    const int bn = blockIdx.x * 128;
    if (MODE == 0 && bn >= SP) return;
    if (MODE == 2 && bm >= SP) return;
    const int K3 = (MODE == 1) ? 3 * SP : ld;

    extern __shared__ char dsm[];
    const uint32_t raw  = smem_u32(dsm);
    const uint32_t base = (raw + 1023u) & ~1023u;
    char* sm = dsm + (base - raw);

    const int tid  = threadIdx.x;
    const int wid  = tid >> 5;
    const int lane = tid & 31;
    const __nv_bfloat16* A  = Ag + bz * sA;
    const __nv_bfloat16* Bp = Bg + bz * sB;

    const int wm = (wid & 1) * 64;
    const int wn = (wid >> 1) * 32;

    float acc[4][4][4];
    #pragma unroll
    for (int i = 0; i < 4; ++i)
        #pragma unroll
        for (int j = 0; j < 4; ++j)
            #pragma unroll
            for (int r = 0; r < 4; ++r) acc[i][j][r] = 0.f;

    const int lr  = tid >> 1;
    const int lc0 = (tid & 1) << 2;
    const int NT  = K3 >> 6;

    auto load_chunk = [&](int kt) {
        const int kc = kt << 6;
        const uint32_t ab = base + (kt % 3) * STAGE;
        const uint32_t bb = ab + 16384;
        const __nv_bfloat16* arow = A  + (size_t)(bm + lr) * ld + kc;
        const __nv_bfloat16* brow = Bp + (size_t)(bn + lr) * ld + kc;
        #pragma unroll
        for (int c = 0; c < 4; ++c) {
            int c16 = lc0 + c;
            uint32_t sw = (uint32_t)((c16 ^ (lr & 7)) << 4);
            CP_ASYNC16(ab + (uint32_t)(lr << 7) + sw, arow + (c16 << 3));
            CP_ASYNC16(bb + (uint32_t)(lr << 7) + sw, brow + (c16 << 3));
        }
        CP_COMMIT();
    };

    load_chunk(0);
    load_chunk(1);

    for (int kt = 0; kt < NT; ++kt) {
        if (kt + 1 < NT) CP_WAIT1();
        else             CP_WAIT0();
        __syncthreads();
        if (kt + 2 < NT) load_chunk(kt + 2);

        const uint32_t ab = base + (kt % 3) * STAGE;
        const uint32_t bb = ab + 16384;
        const int t4 = lane >> 3;

        #pragma unroll
        for (int ks = 0; ks < 4; ++ks) {
            uint32_t Af[4][4];
            #pragma unroll
            for (int mt = 0; mt < 4; ++mt) {
                int row = wm + mt * 16 + ((t4 & 1) << 3) + (lane & 7);
                int c16 = ks * 2 + (t4 >> 1);
                uint32_t addr = ab + (uint32_t)(row << 7)
                              + (uint32_t)((c16 ^ (row & 7)) << 4);
                ldsm_x4(Af[mt][0], Af[mt][1], Af[mt][2], Af[mt][3], addr);
            }
            uint32_t Bf[2][4];
            #pragma unroll
            for (int gt = 0; gt < 2; ++gt) {
                int row = wn + gt * 16 + ((t4 >> 1) << 3) + (lane & 7);
                int c16 = ks * 2 + (t4 & 1);
                uint32_t addr = bb + (uint32_t)(row << 7)
                              + (uint32_t)((c16 ^ (row & 7)) << 4);
                ldsm_x4(Bf[gt][0], Bf[gt][1], Bf[gt][2], Bf[gt][3], addr);
            }
            #pragma unroll
            for (int mt = 0; mt < 4; ++mt)
                #pragma unroll
                for (int ng = 0; ng < 4; ++ng) {
                    const uint32_t* bg = Bf[ng >> 1];
                    mma_bf16(acc[mt][ng],
                             Af[mt][0], Af[mt][1], Af[mt][2], Af[mt][3],
                             bg[(ng & 1) * 2], bg[(ng & 1) * 2 + 1]);
                }
        }
    }
    __syncthreads();

    const int qr = lane >> 2;
    const int qc = (lane & 3) << 1;

    if (MODE == 0 || MODE == 2) {
        float* slab = reinterpret_cast<float*>(sm);   // [m][n] pitch 132
        #pragma unroll
        for (int mt = 0; mt < 4; ++mt)
            #pragma unroll
            for (int ng = 0; ng < 4; ++ng) {
                int m = wm + mt * 16 + qr;
                int n = wn + ng * 8 + qc;
                float* p0 = slab + (size_t)m * 132 + n;
                p0[0] = acc[mt][ng][0] * scale;
                p0[1] = acc[mt][ng][1] * scale;
                float* p1 = p0 + 8 * 132;
                p1[0] = acc[mt][ng][2] * scale;
                p1[1] = acc[mt][ng][3] * scale;
            }
        __syncthreads();
        float* Cb = Cg + bz * sOut;
        const int Sc = (MODE == 2) ? scnt[bz] : 0;
        #pragma unroll
        for (int it = 0; it < 16; ++it) {
            int idx = tid + (it << 8);
            int r = idx >> 5, c = (idx & 31) << 2;
            float4 v = *reinterpret_cast<float4*>(slab + (size_t)r * 132 + c);
            if (MODE == 0) {
                *reinterpret_cast<float4*>(Cb + (size_t)(bm + r) * ldc + bn + c) = v;
            } else {
                int gr = bm + r;
                if (gr < Sc) {
                    int trow = idxb[bz * S_ + gr];
                    *reinterpret_cast<float4*>(Cb + (size_t)trow * ldc + bn + c) = v;
                }
            }
        }
    } else {
        float* slab = reinterpret_cast<float*>(sm);   // [n][m] pitch 132
        #pragma unroll
        for (int mt = 0; mt < 4; ++mt)
            #pragma unroll
            for (int ng = 0; ng < 4; ++ng) {
                int m = wm + mt * 16 + qr;
                int n = wn + ng * 8 + qc;
                slab[(size_t)n * 132 + m]           = acc[mt][ng][0];
                slab[(size_t)(n + 1) * 132 + m]     = acc[mt][ng][1];
                slab[(size_t)n * 132 + m + 8]       = acc[mt][ng][2];
                slab[(size_t)(n + 1) * 132 + m + 8] = acc[mt][ng][3];
            }
        __syncthreads();
        __nv_bfloat16* T = Tg + bz * sOut;
        #pragma unroll
        for (int it = 0; it < 16; ++it) {
            int idx = tid + (it << 8);
            int n = idx >> 5, mc = (idx & 31) << 2;
            float4 v = *reinterpret_cast<float4*>(slab + (size_t)n * 132 + mc);
            float xs[4] = {v.x, v.y, v.z, v.w};
            __align__(8) __nv_bfloat16 h[4], l[4];
            #pragma unroll
            for (int i = 0; i < 4; ++i) {
                h[i] = __float2bfloat16(xs[i]);
                l[i] = __float2bfloat16(xs[i] - __bfloat162float(h[i]));
            }
            __nv_bfloat16* dst = T + (size_t)(bn + n) * K3A + bm + mc;
            *reinterpret_cast<uint2*>(dst)           = *reinterpret_cast<uint2*>(h);
            *reinterpret_cast<uint2*>(dst + LQ_)     = *reinterpret_cast<uint2*>(l);
            *reinterpret_cast<uint2*>(dst + 2 * LQ_) = *reinterpret_cast<uint2*>(h);
        }
    }
}

// ------------- mask prefix scan: pos, idx, Sc, SP per batch -------------
__global__ void __launch_bounds__(256) scan_mask(
    const int* __restrict__ mask, int* __restrict__ pos, int* __restrict__ idxb,
    int* __restrict__ scnt, int* __restrict__ sptab)
{
    const int b = blockIdx.x;
    const int* mp = mask + b * S_;
    const int t = threadIdx.x;
    __shared__ int part[256];
    int loc[8], sum = 0;
    #pragma unroll
    for (int i = 0; i < 8; ++i) { loc[i] = mp[t * 8 + i]; sum += loc[i]; }
    part[t] = sum;
    __syncthreads();
    for (int off = 1; off < 256; off <<= 1) {
        int v = (t >= off) ? part[t - off] : 0;
        __syncthreads();
        part[t] += v;
        __syncthreads();
    }
    int run = part[t] - sum;            // exclusive base
    #pragma unroll
    for (int i = 0; i < 8; ++i) {
        int s = t * 8 + i;
        pos[b * S_ + s] = run;
        if (loc[i]) { idxb[b * S_ + run] = s; ++run; }
    }
    if (t == 255) {
        scnt[b]  = run;
        sptab[b] = (run + 127) & ~127;
    }
}

// ------------- Q split A-role [h|h|l], pitch 3*Dn -------------
__global__ void __launch_bounds__(256) split_rows_q(
    const float* __restrict__ in, __nv_bfloat16* __restrict__ out)
{
    size_t idx = (size_t)blockIdx.x * 256 + threadIdx.x;
    size_t row = idx >> 8;                  // D/4 = 256 float4 per row
    int    c   = (int)(idx & 255) << 2;
    float4 v = *reinterpret_cast<const float4*>(in + row * D_ + c);
    float xs[4] = {v.x, v.y, v.z, v.w};
    __align__(8) __nv_bfloat16 h[4], l[4];
    #pragma unroll
    for (int i = 0; i < 4; ++i) {
        h[i] = __float2bfloat16(xs[i]);
        l[i] = __float2bfloat16(xs[i] - __bfloat162float(h[i]));
    }
    __nv_bfloat16* o = out + row * (size_t)K3QK + c;
    *reinterpret_cast<uint2*>(o)          = *reinterpret_cast<uint2*>(h);
    *reinterpret_cast<uint2*>(o + D_)     = *reinterpret_cast<uint2*>(h);
    *reinterpret_cast<uint2*>(o + 2 * D_) = *reinterpret_cast<uint2*>(l);
}

// ------------- K gather+split B-role [h|l|h]: row j <- K[idx[j]] -------------
__global__ void __launch_bounds__(256) gather_split_k(
    const float* __restrict__ k, __nv_bfloat16* __restrict__ out,
    const int* __restrict__ idxb, const int* __restrict__ scnt,
    const int* __restrict__ sptab)
{
    const int b = blockIdx.y, j = blockIdx.x;
    if (j >= sptab[b]) return;
    const int t = threadIdx.x, c = t << 2;
    __nv_bfloat16* o = out + ((size_t)b * S_ + j) * K3QK + c;
    __align__(8) __nv_bfloat16 h[4], l[4];
    if (j < scnt[b]) {
        const float* src = k + ((size_t)b * S_ + idxb[b * S_ + j]) * D_ + c;
        float4 v = *reinterpret_cast<const float4*>(src);
        float xs[4] = {v.x, v.y, v.z, v.w};
        #pragma unroll
        for (int i = 0; i < 4; ++i) {
            h[i] = __float2bfloat16(xs[i]);
            l[i] = __float2bfloat16(xs[i] - __bfloat162float(h[i]));
        }
    } else {
        #pragma unroll
        for (int i = 0; i < 4; ++i) { h[i] = __float2bfloat16(0.f); l[i] = h[i]; }
    }
    *reinterpret_cast<uint2*>(o)          = *reinterpret_cast<uint2*>(h);
    *reinterpret_cast<uint2*>(o + D_)     = *reinterpret_cast<uint2*>(l);
    *reinterpret_cast<uint2*>(o + 2 * D_) = *reinterpret_cast<uint2*>(h);
}

// ------------- V gather + transpose + split B-role [h|l|h], seg pitch SP ----
__global__ void __launch_bounds__(256) gather_tsplit_v(
    const float* __restrict__ v, __nv_bfloat16* __restrict__ out,
    const int* __restrict__ idxb, const int* __restrict__ scnt,
    const int* __restrict__ sptab)
{
    const int b  = blockIdx.z;
    const int SP = sptab[b], Sc = scnt[b];
    const int j0 = blockIdx.x * 32;
    if (j0 >= SP) return;
    const int d0 = blockIdx.y * 32;
    const float* ip = v + (size_t)b * S_ * D_;
    __nv_bfloat16* op = out + (size_t)b * D_ * K3A;
    __shared__ float tile[32][33];
    const int tx = threadIdx.x & 31, ty = threadIdx.x >> 5;
    #pragma unroll
    for (int i = 0; i < 4; ++i) {
        int jr = j0 + ty + i * 8;
        float val = 0.f;
        if (jr < Sc) val = ip[(size_t)idxb[b * S_ + jr] * D_ + d0 + tx];
        tile[ty + i * 8][tx] = val;
    }
    __syncthreads();
    #pragma unroll
    for (int i = 0; i < 4; ++i) {
        int cc = ty + i * 8;
        float x = tile[tx][cc];                        // = V[j0+tx][d0+cc]
        __nv_bfloat16 h = __float2bfloat16(x);
        __nv_bfloat16 l = __float2bfloat16(x - __bfloat162float(h));
        __nv_bfloat16* o = op + (size_t)(d0 + cc) * K3A + j0 + tx;
        o[0]      = h;
        o[SP]     = l;
        o[2 * SP] = h;
    }
}

// ------------- softmax over compacted row + full-aw scatter + A-role split ---
__global__ void __launch_bounds__(256) softmax_compact(
    float* __restrict__ awc, float* __restrict__ aw, const int* __restrict__ mask,
    __nv_bfloat16* __restrict__ aws, const int* __restrict__ pos,
    const int* __restrict__ scnt, const int* __restrict__ sptab)
{
    const int row = blockIdx.x;
    const int b   = row >> 11;
    const int Sc  = scnt[b], SP = sptab[b];
    float*         cp = awc + (size_t)row * S_;
    float*         rp = aw  + (size_t)row * S_;
    __nv_bfloat16* ap = aws + (size_t)row * K3A;
    const int*     mp = mask + b * S_;
    const int*     pp = pos  + b * S_;
    const int t = threadIdx.x;
    const float NEG_INF = __int_as_float(0xff800000);

    __shared__ float parr[2048];
    __shared__ float smax[8], ssum[8];

    float vv[8];
    float mx = NEG_INF;
    #pragma unroll
    for (int i = 0; i < 8; ++i) {
        int j = t + (i << 8);
        vv[i] = (j < Sc) ? cp[j] : NEG_INF;
        mx = fmaxf(mx, vv[i]);
    }
    #pragma unroll
    for (int off = 16; off > 0; off >>= 1)
        mx = fmaxf(mx, __shfl_xor_sync(0xffffffffu, mx, off));
    if ((t & 31) == 0) smax[t >> 5] = mx;
    __syncthreads();
    float rmax = smax[0];
    #pragma unroll
    for (int i = 1; i < 8; ++i) rmax = fmaxf(rmax, smax[i]);

    float e[8], sum = 0.f;
    #pragma unroll
    for (int i = 0; i < 8; ++i) {
        int j = t + (i << 8);
        e[i] = (j < Sc) ? __expf(vv[i] - rmax) : 0.f;
        sum += e[i];
    }
    #pragma unroll
    for (int off = 16; off > 0; off >>= 1)
        sum += __shfl_xor_sync(0xffffffffu, sum, off);
    if ((t & 31) == 0) ssum[t >> 5] = sum;
    __syncthreads();
    float rsum = 0.f;
    #pragma unroll
    for (int i = 0; i < 8; ++i) rsum += ssum[i];
    const float inv = 1.f / rsum;

    #pragma unroll
    for (int i = 0; i < 8; ++i) {
        int j = t + (i << 8);
        if (j < SP) {
            float p = e[i] * inv;          // 0 for j >= Sc
            cp[j]   = p;
            parr[j] = p;
            __nv_bfloat16 h = __float2bfloat16(p);
            __nv_bfloat16 l = __float2bfloat16(p - __bfloat162float(h));
            ap[j]          = h;            // A-role [h | h | l], seg pitch SP
            ap[SP + j]     = h;
            ap[2 * SP + j] = l;
        }
    }
    __syncthreads();
    #pragma unroll
    for (int i = 0; i < 8; ++i) {
        int s = t + (i << 8);
        rp[s] = mp[s] ? parr[pp[s]] : 0.f;
    }
}

// ------------- transpose+split awc -> awts A-role [h|h|l], col-limit SP -----
__global__ void __launch_bounds__(256) tsplit_awc(
    const float* __restrict__ awc, __nv_bfloat16* __restrict__ out,
    const int* __restrict__ sptab)
{
    const int b  = blockIdx.z;
    const int c0 = blockIdx.y * 32;          // j (compacted s)
    if (c0 >= sptab[b]) return;
    const int r0 = blockIdx.x * 32;          // q
    const float* ip = awc + (size_t)b * LQ_ * S_;
    __nv_bfloat16* op = out + (size_t)b * S_ * K3A;
    __shared__ float tile[32][33];
    const int tx = threadIdx.x & 31, ty = threadIdx.x >> 5;
    #pragma unroll
    for (int i = 0; i < 4; ++i)
        tile[ty + i * 8][tx] = ip[(size_t)(r0 + ty + i * 8) * S_ + c0 + tx];
    __syncthreads();
    #pragma unroll
    for (int i = 0; i < 4; ++i) {
        int cc = ty + i * 8;
        float x = tile[tx][cc];
        __nv_bfloat16 h = __float2bfloat16(x);
        __nv_bfloat16 l = __float2bfloat16(x - __bfloat162float(h));
        __nv_bfloat16* o = op + (size_t)(c0 + cc) * K3A + r0 + tx;
        o[0]       = h;
        o[LQ_]     = h;
        o[2 * LQ_] = l;
    }
}

// ------------- zero output rows where mask == 0 -------------
__global__ void __launch_bounds__(256) zero_masked(
    float* __restrict__ out, const int* __restrict__ mask)
{
    const int b = blockIdx.y, s = blockIdx.x;
    if (mask[b * S_ + s]) return;
    float* r = out + ((size_t)b * S_ + s) * D_;
    float4 z = make_float4(0.f, 0.f, 0.f, 0.f);
    *reinterpret_cast<float4*>(r + (threadIdx.x << 2)) = z;
}

extern "C" void kernel_launch(void* const* d_in, const int* in_sizes, int n_in,
                              void* d_out, int out_size)
{
    const float* q    = (const float*)d_in[0];
    const float* kk   = (const float*)d_in[1];
    const float* v    = (const float*)d_in[2];
    const int*   mask = (const int*)  d_in[3];

    float* out = (float*)d_out;                       // output [B,S,D]
    float* aw  = out + (size_t)B_ * S_ * D_;          // attention_weights [B,LQ,S]

    void* p;
    cudaGetSymbolAddress(&p, g_qs);   __nv_bfloat16* qs   = (__nv_bfloat16*)p;
    cudaGetSymbolAddress(&p, g_ks);   __nv_bfloat16* ks   = (__nv_bfloat16*)p;
    cudaGetSymbolAddress(&p, g_vts);  __nv_bfloat16* vts  = (__nv_bfloat16*)p;
    cudaGetSymbolAddress(&p, g_aws);  __nv_bfloat16* aws  = (__nv_bfloat16*)p;
    cudaGetSymbolAddress(&p, g_awts); __nv_bfloat16* awts = (__nv_bfloat16*)p;
    cudaGetSymbolAddress(&p, g_o1ts); __nv_bfloat16* o1ts = (__nv_bfloat16*)p;
    cudaGetSymbolAddress(&p, g_awc);  float* awc  = (float*)p;
    cudaGetSymbolAddress(&p, g_pos);  int*   pos  = (int*)p;
    cudaGetSymbolAddress(&p, g_idx);  int*   idxb = (int*)p;
    cudaGetSymbolAddress(&p, g_scnt); int*   scnt = (int*)p;
    cudaGetSymbolAddress(&p, g_sp);   int*   sp   = (int*)p;

    cudaFuncSetAttribute(gemm_mma<0>, cudaFuncAttributeMaxDynamicSharedMemorySize, SMEM_SZ);
    cudaFuncSetAttribute(gemm_mma<1>, cudaFuncAttributeMaxDynamicSharedMemorySize, SMEM_SZ);
    cudaFuncSetAttribute(gemm_mma<2>, cudaFuncAttributeMaxDynamicSharedMemorySize, SMEM_SZ);

    // 0) mask scan: pos/idx/Sc/SP per batch
    scan_mask<<<B_, 256>>>(mask, pos, idxb, scnt, sp);

    // 1) operand prep
    split_rows_q<<<(int)(((size_t)B_ * LQ_ * D_ / 4) / 256), 256>>>(q, qs);
    gather_split_k<<<dim3(S_, B_), 256>>>(kk, ks, idxb, scnt, sp);
    gather_tsplit_v<<<dim3(S_ / 32, D_ / 32, B_), 256>>>(v, vts, idxb, scnt, sp);

    // 2) scores_c = Q @ Kc^T / 32 -> awc (compact N)
    gemm_mma<0><<<dim3(S_ / 128, LQ_ / 128, B_), 256, SMEM_SZ>>>(
        qs, ks, awc, nullptr, K3QK, S_,
        (size_t)LQ_ * K3QK, (size_t)S_ * K3QK, (size_t)LQ_ * S_, 0.03125f,
        scnt, sp, idxb);

    // 3) softmax on compacted row; scatter full aw; write A-role split
    softmax_compact<<<B_ * LQ_, 256>>>(awc, aw, mask, aws, pos, scnt, sp);

    // 4) awc^T split (A-role, compacted rows)
    tsplit_awc<<<dim3(LQ_ / 32, S_ / 32, B_), 256>>>(awc, awts, sp);

    // 5) out1 = awc @ Vc (compact K = 3*SP) -> o1ts (bf16 split-T, B-role)
    gemm_mma<1><<<dim3(D_ / 128, LQ_ / 128, B_), 256, SMEM_SZ>>>(
        aws, vts, nullptr, o1ts, K3A, 0,
        (size_t)LQ_ * K3A, (size_t)D_ * K3A, (size_t)D_ * K3A, 1.0f,
        scnt, sp, idxb);

    // 6) zero masked output rows; compute unmasked rows scattered via idx
    zero_masked<<<dim3(S_, B_), 256>>>(out, mask);
    gemm_mma<2><<<dim3(D_ / 128, S_ / 128, B_), 256, SMEM_SZ>>>(
        awts, o1ts, out, nullptr, K3A, D_,
        (size_t)S_ * K3A, (size_t)D_ * K3A, (size_t)S_ * D_, 1.0f,
        scnt, sp, idxb);
}